// round 11
// baseline (speedup 1.0000x reference)
#include <cuda_runtime.h>
#include <cuda_fp16.h>
#include <cstdint>

// ---------------------------------------------------------------------------
// Fused MoE gate via 3-term fp16 split mma (m16n8k16), R10-proven numerics
// (bit-identical): per K32 blk: tm = 2-chain main, tc0/tc1 = 2-chain
// corrections, long-range K accumulation in fp32 FADDs.
//   x*(64w) = h0x*h0w + h0x*h1w + h1x*h0w   [h1x*h1w ~ 2^-22, dropped]
// X is loaded RAW (fp32) via cp.async and split at consume time (no xsplit
// kernel, no 256MB scratch). W pre-split once into a packed fp16x2 image.
// Serial-mt keeps live registers ~115 (no spills at the 128-reg cap).
// out (float32): [0..T*8) = topk_idx (as float), [T*8..2T*8) = weights*2.5
// ---------------------------------------------------------------------------

#define KD    4096
#define NE    256
#define BM    128
#define NST   64                  // K64 stages

#define A_PITCH_F 72              // 64 fp32 + 8 pad (288 B/row)
#define A_SMEM    (128 * A_PITCH_F * 4)         // 36864
#define B_PITCH_W 72              // 64 u32 + 8 pad (288 B/row)
#define B_SMEM    (256 * B_PITCH_W * 4)         // 73728
#define STAGE_SZ  (A_SMEM + B_SMEM)             // 110592
#define OFF_BIAS  0
#define OFF_STAGE 1024
#define SMEM_TOTAL (OFF_STAGE + 2 * STAGE_SZ)   // 222208

// W image: per (K32-block kb, row n): 32 u32 words,
//   word = ks*16 + plane*8 + pos, pair p at pos = (p%4)*2 + p/4, k = kb*32+...
__device__ __align__(16) uint32_t g_wsplit[(size_t)128 * 256 * 32];  // 4 MB

__device__ __forceinline__ uint32_t smem_u32(const void* p) {
    uint32_t a;
    asm("{ .reg .u64 t; cvta.to.shared.u64 t, %1; cvt.u32.u64 %0, t; }"
        : "=r"(a) : "l"(p));
    return a;
}
__device__ __forceinline__ void lds_v2(uint32_t a, uint32_t& x, uint32_t& y) {
    asm volatile("ld.shared.v2.u32 {%0,%1}, [%2];" : "=r"(x), "=r"(y) : "r"(a));
}
__device__ __forceinline__ void lds_v2f(uint32_t a, float& x, float& y) {
    asm volatile("ld.shared.v2.f32 {%0,%1}, [%2];" : "=f"(x), "=f"(y) : "r"(a));
}
__device__ __forceinline__ void mma_acc(float* d, const uint32_t* a,
                                        uint32_t b0, uint32_t b1) {
    asm volatile(
        "mma.sync.aligned.m16n8k16.row.col.f32.f16.f16.f32 "
        "{%0,%1,%2,%3}, {%4,%5,%6,%7}, {%8,%9}, {%0,%1,%2,%3};"
        : "+f"(d[0]), "+f"(d[1]), "+f"(d[2]), "+f"(d[3])
        : "r"(a[0]), "r"(a[1]), "r"(a[2]), "r"(a[3]), "r"(b0), "r"(b1));
}
__device__ __forceinline__ void mma_zro(float* d, const uint32_t* a,
                                        uint32_t b0, uint32_t b1) {
    asm volatile(
        "mma.sync.aligned.m16n8k16.row.col.f32.f16.f16.f32 "
        "{%0,%1,%2,%3}, {%4,%5,%6,%7}, {%8,%9}, {%10,%11,%12,%13};"
        : "=f"(d[0]), "=f"(d[1]), "=f"(d[2]), "=f"(d[3])
        : "r"(a[0]), "r"(a[1]), "r"(a[2]), "r"(a[3]), "r"(b0), "r"(b1),
          "f"(0.0f), "f"(0.0f), "f"(0.0f), "f"(0.0f));
}

// split an fp32 pair into packed fp16x2 (h0, h1) — identical math to R10
__device__ __forceinline__ void split_pair(float x0, float x1,
                                           uint32_t& h0, uint32_t& h1) {
    __half2 a = __floats2half2_rn(x0, x1);           // lo = x0
    h0 = *reinterpret_cast<uint32_t*>(&a);
    float r0 = x0 - __half2float(__low2half(a));
    float r1 = x1 - __half2float(__high2half(a));
    __half2 b = __floats2half2_rn(r0, r1);
    h1 = *reinterpret_cast<uint32_t*>(&b);
}

// ---------------- W pre-split (scaled by 64; unscaled in epilogue) ---------
__global__ __launch_bounds__(256)
void wsplit_kernel(const float* __restrict__ W) {
    size_t id = (size_t)blockIdx.x * 256 + threadIdx.x;   // 128*256*32 total
    int w  = (int)(id & 31);
    size_t rn = id >> 5;
    int n  = (int)(rn & 255);
    int kb = (int)(rn >> 8);
    int half = w >> 4, plane = (w >> 3) & 1, pos = w & 7;
    int p = ((pos & 1) << 2) | (pos >> 1);
    int k = kb * 32 + half * 16 + p * 2;
    float x0 = W[(size_t)n * KD + k] * 64.0f;
    float x1 = W[(size_t)n * KD + k + 1] * 64.0f;
    uint32_t h0, h1;
    split_pair(x0, x1, h0, h1);
    g_wsplit[id] = plane ? h1 : h0;
}

// ------------------------------- main kernel -------------------------------
__global__ __launch_bounds__(512, 1)
void moe_kernel(const float* __restrict__ X, const float* __restrict__ bias,
                float* __restrict__ out, int T)
{
    extern __shared__ char sm[];
    const uint32_t sb = smem_u32(sm);
    const int tid = threadIdx.x, wid = tid >> 5, lane = tid & 31;
    const int wm = wid & 3, wn = wid >> 2;           // 4x4 warp grid
    const int m0 = blockIdx.x * BM;
    const int fr = lane >> 2, fc = lane & 3;

    if (tid < NE) ((float*)(sm + OFF_BIAS))[tid] = bias[tid];

#define ISSUE(s) do {                                                          \
    uint32_t stb_ = sb + OFF_STAGE + ((s) & 1) * STAGE_SZ;                     \
    _Pragma("unroll")                                                          \
    for (int i_ = 0; i_ < 4; i_++) {       /* A raw fp32: 128 rows x 256B */   \
        int id_ = tid + i_ * 512;                                              \
        int r_ = id_ >> 4, c_ = id_ & 15;                                      \
        const float* src_ = X + (size_t)(m0 + r_) * KD + (s) * 64 + c_ * 4;    \
        asm volatile("cp.async.cg.shared.global [%0], [%1], 16;"               \
            :: "r"(stb_ + r_ * (A_PITCH_F * 4) + c_ * 16), "l"(src_));         \
    }                                                                          \
    _Pragma("unroll")                                                          \
    for (int i_ = 0; i_ < 8; i_++) {       /* B image: 256 rows x 256B */      \
        int id_ = tid + i_ * 512;                                              \
        int n_ = id_ >> 4, c_ = id_ & 15;                                      \
        const uint32_t* src_ = g_wsplit                                        \
            + (((size_t)(s) * 2 + (c_ >> 3)) * 256 + n_) * 32 + (c_ & 7) * 4;  \
        asm volatile("cp.async.cg.shared.global [%0], [%1], 16;"               \
            :: "r"(stb_ + A_SMEM + n_ * (B_PITCH_W * 4) + c_ * 16), "l"(src_));\
    }                                                                          \
} while (0)

    ISSUE(0); asm volatile("cp.async.commit_group;" ::: "memory");
    ISSUE(1); asm volatile("cp.async.commit_group;" ::: "memory");

    float acc[2][8][4];
#pragma unroll
    for (int i = 0; i < 2; i++)
#pragma unroll
        for (int j = 0; j < 8; j++)
#pragma unroll
            for (int q = 0; q < 4; q++) acc[i][j][q] = 0.0f;

    for (int s = 0; s < NST; s++) {
        asm volatile("cp.async.wait_group 1;" ::: "memory");
        __syncthreads();
        const uint32_t stb = sb + OFF_STAGE + (s & 1) * STAGE_SZ;
        const uint32_t sB  = stb + A_SMEM;

#pragma unroll
        for (int blk = 0; blk < 2; blk++) {          // two K32 halves
#pragma unroll
            for (int mt = 0; mt < 2; mt++) {         // serial-mt (reg relief)
                const int r0 = (wm * 2 + mt) * 16 + fr;
                // ---- load raw A + split to fp16 fragments (16 regs) ----
                uint32_t AH[2][4], AL[2][4];
#pragma unroll
                for (int ks = 0; ks < 2; ks++) {
                    uint32_t ab = stb + (uint32_t)r0 * (A_PITCH_F * 4)
                                + (uint32_t)(blk * 32 + ks * 16 + fc * 2) * 4;
                    float x0, x1;
                    lds_v2f(ab, x0, x1);                       // row r0,  k
                    split_pair(x0, x1, AH[ks][0], AL[ks][0]);
                    lds_v2f(ab + 8 * A_PITCH_F * 4, x0, x1);   // row r0+8, k
                    split_pair(x0, x1, AH[ks][1], AL[ks][1]);
                    lds_v2f(ab + 32, x0, x1);                  // row r0,  k+8
                    split_pair(x0, x1, AH[ks][2], AL[ks][2]);
                    lds_v2f(ab + 8 * A_PITCH_F * 4 + 32, x0, x1);
                    split_pair(x0, x1, AH[ks][3], AL[ks][3]);  // row r0+8,k+8
                }
#pragma unroll
                for (int nt = 0; nt < 8; nt++) {
                    const int n = (wn * 8 + nt) * 8 + fr;
                    uint32_t bb = sB + (uint32_t)n * (B_PITCH_W * 4)
                                + blk * 128 + fc * 8;
                    uint32_t BH[2][2], BL[2][2];
                    lds_v2(bb,      BH[0][0], BH[0][1]);   // ks0 h0
                    lds_v2(bb + 32, BL[0][0], BL[0][1]);   // ks0 h1
                    lds_v2(bb + 64, BH[1][0], BH[1][1]);   // ks1 h0
                    lds_v2(bb + 96, BL[1][0], BL[1][1]);   // ks1 h1

                    float tm[4], tc0[4], tc1[4];
                    mma_zro(tm,  AH[0], BH[0][0], BH[0][1]);  // h0*h0 ks0
                    mma_acc(tm,  AH[1], BH[1][0], BH[1][1]);  // h0*h0 ks1
                    mma_zro(tc0, AH[0], BL[0][0], BL[0][1]);  // h0*h1 ks0
                    mma_acc(tc0, AL[0], BH[0][0], BH[0][1]);  // h1*h0 ks0
                    mma_zro(tc1, AH[1], BL[1][0], BL[1][1]);  // h0*h1 ks1
                    mma_acc(tc1, AL[1], BH[1][0], BH[1][1]);  // h1*h0 ks1
#pragma unroll
                    for (int q = 0; q < 4; q++)
                        acc[mt][nt][q] += tm[q] + tc0[q] + tc1[q];
                }
            }
        }

        __syncthreads();
        if (s + 2 < NST) ISSUE(s + 2);
        asm volatile("cp.async.commit_group;" ::: "memory");
    }
#undef ISSUE

    // ---------------- dump logits (unscale by 1/64) to smem ---------------
    {
        float* sc = (float*)(sm + OFF_STAGE);
        const float inv = 1.0f / 64.0f;
#pragma unroll
        for (int mt = 0; mt < 2; mt++) {
            int r = wm * 32 + mt * 16 + fr;
#pragma unroll
            for (int nt = 0; nt < 8; nt++) {
                int c = wn * 64 + nt * 8 + fc * 2;
                sc[r * 257 + c]           = acc[mt][nt][0] * inv;
                sc[r * 257 + c + 1]       = acc[mt][nt][1] * inv;
                sc[(r + 8) * 257 + c]     = acc[mt][nt][2] * inv;
                sc[(r + 8) * 257 + c + 1] = acc[mt][nt][3] * inv;
            }
        }
    }
    __syncthreads();

    // ---------------- fused gating (warps 0-3, one token per thread) ------
    if (wid < 4) {
        const int row = wid * 32 + lane;
        float* srow = (float*)(sm + OFF_STAGE) + row * 257;
        const float* bs = (const float*)(sm + OFF_BIAS);

        float gs[8];
#pragma unroll
        for (int g = 0; g < 8; g++) {
            float m1 = -1e30f, m2 = -1e30f;
#pragma unroll
            for (int i = 0; i < 32; i++) {
                float lg = srow[g * 32 + i];
                float scv = 1.0f / (1.0f + expf(-lg));   // sigmoid
                float v = scv + bs[g * 32 + i];          // scores_for_choice
                srow[g * 32 + i] = v;
                if (v > m1) { m2 = m1; m1 = v; }
                else if (v > m2) m2 = v;
            }
            gs[g] = m1 + m2;
        }
        int mask = 0;
#pragma unroll
        for (int j = 0; j < 8; j++) {
            int rk = 0;
#pragma unroll
            for (int j2 = 0; j2 < 8; j2++)
                rk += (gs[j2] > gs[j]) || (gs[j2] == gs[j] && j2 < j);
            if (rk < 4) mask |= 1 << j;
        }
        float bv[8]; int bi[8];
#pragma unroll
        for (int k = 0; k < 8; k++) { bv[k] = -1e30f; bi[k] = 0; }
        for (int e = 0; e < NE; e++) {
            float v = ((mask >> (e >> 5)) & 1) ? srow[e] : 0.0f;
            if (v > bv[7]) {
                bv[7] = v; bi[7] = e;
#pragma unroll
                for (int k = 7; k > 0; k--)
                    if (bv[k] > bv[k - 1]) {
                        float tv = bv[k]; bv[k] = bv[k - 1]; bv[k - 1] = tv;
                        int ti = bi[k];  bi[k] = bi[k - 1]; bi[k - 1] = ti;
                    }
            }
        }
        float ws = 0.0f, wv[8];
#pragma unroll
        for (int k = 0; k < 8; k++) { wv[k] = bv[k] - bs[bi[k]]; ws += wv[k]; }
        const size_t token = (size_t)(m0 + row);
#pragma unroll
        for (int k = 0; k < 8; k++) {
            out[token * 8 + k] = (float)bi[k];
            out[(size_t)T * 8 + token * 8 + k] = wv[k] / (ws + 1e-20f) * 2.5f;
        }
    }
}

extern "C" void kernel_launch(void* const* d_in, const int* in_sizes, int n_in,
                              void* d_out, int out_size)
{
    const float* X    = (const float*)d_in[0];
    const float* W    = (const float*)d_in[1];
    const float* bias = (const float*)d_in[2];
    float* out = (float*)d_out;

    const int T = in_sizes[0] / KD;   // 16384

    wsplit_kernel<<<(128 * 256 * 32) / 256, 256>>>(W);

    cudaFuncSetAttribute(moe_kernel,
                         cudaFuncAttributeMaxDynamicSharedMemorySize, SMEM_TOTAL);
    moe_kernel<<<T / BM, 512, SMEM_TOTAL>>>(X, bias, out, T);
}

// round 12
// speedup vs baseline: 1.0698x; 1.0698x over previous
#include <cuda_runtime.h>
#include <cuda_fp16.h>
#include <cstdint>

// ---------------------------------------------------------------------------
// MoE gate, split-N for occupancy: GEMM CTAs cover 64 tokens x 128 experts
// (acc=32 regs/thread, 3 CTAs/SM = 24 warps/SM), logits to global scratch,
// warp-per-token gate kernel (R2-proven). Numerics = R10 (bit-identical):
//   x*(64w) = h0x*h0w + h0x*h1w + h1x*h0w, per-K32 tm/tc0/tc1 2-chains,
//   long-range K accumulation in fp32 FADDs.
// out (float32): [0..T*8) = topk_idx (as float), [T*8..2T*8) = weights*2.5
// ---------------------------------------------------------------------------

#define KD    4096
#define NE    256
#define NST   128                 // K32 stages
#define TMAX  16384

#define PITCH_B   160             // 32 u32 data + 8 pad words per row
#define A_SMEM    (64 * PITCH_B)                // 10240
#define B_SMEM    (128 * PITCH_B)               // 20480
#define STAGE_SZ  (A_SMEM + B_SMEM)             // 30720
#define OFF_STAGE 1024
#define SMEM_TOTAL (OFF_STAGE + 2 * STAGE_SZ)   // 62464

// images: [(row_kb)*32 + word], word = ks*16 + plane*8 + pos,
//         pair p at pos = ((p&3)<<1)|(p>>2)   (p covers k = 2p within k16)
__device__ __align__(16) uint32_t g_xsplit[(size_t)TMAX * 128 * 32]; // 256 MB
__device__ __align__(16) uint32_t g_wsplit[(size_t)128 * 256 * 32];  //   4 MB
__device__ __align__(16) float    g_logits[(size_t)TMAX * NE];       //  16 MB

__device__ __forceinline__ uint32_t smem_u32(const void* p) {
    uint32_t a;
    asm("{ .reg .u64 t; cvta.to.shared.u64 t, %1; cvt.u32.u64 %0, t; }"
        : "=r"(a) : "l"(p));
    return a;
}
__device__ __forceinline__ void lds_v2(uint32_t a, uint32_t& x, uint32_t& y) {
    asm volatile("ld.shared.v2.u32 {%0,%1}, [%2];" : "=r"(x), "=r"(y) : "r"(a));
}
__device__ __forceinline__ void mma_acc(float* d, const uint32_t* a,
                                        uint32_t b0, uint32_t b1) {
    asm volatile(
        "mma.sync.aligned.m16n8k16.row.col.f32.f16.f16.f32 "
        "{%0,%1,%2,%3}, {%4,%5,%6,%7}, {%8,%9}, {%0,%1,%2,%3};"
        : "+f"(d[0]), "+f"(d[1]), "+f"(d[2]), "+f"(d[3])
        : "r"(a[0]), "r"(a[1]), "r"(a[2]), "r"(a[3]), "r"(b0), "r"(b1));
}
__device__ __forceinline__ void mma_zro(float* d, const uint32_t* a,
                                        uint32_t b0, uint32_t b1) {
    asm volatile(
        "mma.sync.aligned.m16n8k16.row.col.f32.f16.f16.f32 "
        "{%0,%1,%2,%3}, {%4,%5,%6,%7}, {%8,%9}, {%10,%11,%12,%13};"
        : "=f"(d[0]), "=f"(d[1]), "=f"(d[2]), "=f"(d[3])
        : "r"(a[0]), "r"(a[1]), "r"(a[2]), "r"(a[3]), "r"(b0), "r"(b1),
          "f"(0.0f), "f"(0.0f), "f"(0.0f), "f"(0.0f));
}

// ---------------- vectorized X pre-split (R10-proven) ----------------------
__global__ __launch_bounds__(256)
void xsplit_kernel(const float* __restrict__ X, int T) {
    size_t id = (size_t)blockIdx.x * 256 + threadIdx.x;
    int half = (int)(id & 1);
    int kb   = (int)((id >> 1) & 127);
    size_t m = id >> 8;
    if (m >= (size_t)T) return;

    const float4* src = (const float4*)(X + m * KD + kb * 32 + half * 16);
    float4 f0 = src[0], f1 = src[1], f2 = src[2], f3 = src[3];
    float x[16] = {f0.x,f0.y,f0.z,f0.w, f1.x,f1.y,f1.z,f1.w,
                   f2.x,f2.y,f2.z,f2.w, f3.x,f3.y,f3.z,f3.w};
    uint32_t p0[8], p1[8];
#pragma unroll
    for (int p = 0; p < 8; p++) {
        float a = x[2*p], b = x[2*p+1];
        __half2 h0 = __floats2half2_rn(a, b);
        p0[p] = *reinterpret_cast<uint32_t*>(&h0);
        float r0 = a - __half2float(__low2half(h0));
        float r1 = b - __half2float(__high2half(h0));
        __half2 h1 = __floats2half2_rn(r0, r1);
        p1[p] = *reinterpret_cast<uint32_t*>(&h1);
    }
    uint4* dst = (uint4*)(g_xsplit + ((m * 128 + kb) * 32) + half * 16);
    dst[0] = make_uint4(p0[0], p0[4], p0[1], p0[5]);
    dst[1] = make_uint4(p0[2], p0[6], p0[3], p0[7]);
    dst[2] = make_uint4(p1[0], p1[4], p1[1], p1[5]);
    dst[3] = make_uint4(p1[2], p1[6], p1[3], p1[7]);
}

// ---------------- W pre-split (scaled by 64; unscaled later) ---------------
__global__ __launch_bounds__(256)
void wsplit_kernel(const float* __restrict__ W) {
    size_t id = (size_t)blockIdx.x * 256 + threadIdx.x;   // 128*256*32
    int w  = (int)(id & 31);
    size_t rn = id >> 5;
    int n  = (int)(rn & 255);
    int kb = (int)(rn >> 8);
    int half = w >> 4, plane = (w >> 3) & 1, pos = w & 7;
    int p = ((pos & 1) << 2) | (pos >> 1);
    int k = kb * 32 + half * 16 + p * 2;
    float x0 = W[(size_t)n * KD + k] * 64.0f;
    float x1 = W[(size_t)n * KD + k + 1] * 64.0f;
    __half2 h0 = __floats2half2_rn(x0, x1);
    uint32_t v;
    if (plane == 0) v = *reinterpret_cast<uint32_t*>(&h0);
    else {
        float r0 = x0 - __half2float(__low2half(h0));
        float r1 = x1 - __half2float(__high2half(h0));
        __half2 h1 = __floats2half2_rn(r0, r1);
        v = *reinterpret_cast<uint32_t*>(&h1);
    }
    g_wsplit[id] = v;
}

// ------------------------------- GEMM kernel -------------------------------
__global__ __launch_bounds__(256, 3)
void gemm_kernel(int T)
{
    extern __shared__ char sm[];
    const uint32_t sb = smem_u32(sm);
    const int tid = threadIdx.x, wid = tid >> 5, lane = tid & 31;
    const int wm = wid & 3, wn = wid >> 2;           // 4x2 warp grid
    const int m0 = (blockIdx.x >> 1) * 64;
    const int n0 = (blockIdx.x & 1) * 128;
    const int fr = lane >> 2, fc = lane & 3;

#define ISSUE(s) do {                                                          \
    uint32_t stb_ = sb + OFF_STAGE + ((s) & 1) * STAGE_SZ;                     \
    _Pragma("unroll")                                                          \
    for (int i_ = 0; i_ < 2; i_++) {       /* A image: 64 rows x 128B */       \
        int id_ = tid + i_ * 256;                                              \
        int r_ = id_ >> 3, c_ = id_ & 7;                                       \
        const uint32_t* src_ = g_xsplit                                        \
            + ((size_t)(m0 + r_) * 128 + (s)) * 32 + c_ * 4;                   \
        asm volatile("cp.async.cg.shared.global [%0], [%1], 16;"               \
            :: "r"(stb_ + r_ * PITCH_B + c_ * 16), "l"(src_));                 \
    }                                                                          \
    _Pragma("unroll")                                                          \
    for (int i_ = 0; i_ < 4; i_++) {       /* B image: 128 rows x 128B */      \
        int id_ = tid + i_ * 256;                                              \
        int n_ = id_ >> 3, c_ = id_ & 7;                                       \
        const uint32_t* src_ = g_wsplit                                        \
            + ((size_t)(s) * 256 + n0 + n_) * 32 + c_ * 4;                     \
        asm volatile("cp.async.cg.shared.global [%0], [%1], 16;"               \
            :: "r"(stb_ + A_SMEM + n_ * PITCH_B + c_ * 16), "l"(src_));        \
    }                                                                          \
} while (0)

    ISSUE(0); asm volatile("cp.async.commit_group;" ::: "memory");
    ISSUE(1); asm volatile("cp.async.commit_group;" ::: "memory");

    float acc[8][4];
#pragma unroll
    for (int j = 0; j < 8; j++)
#pragma unroll
        for (int q = 0; q < 4; q++) acc[j][q] = 0.0f;

    for (int s = 0; s < NST; s++) {
        asm volatile("cp.async.wait_group 1;" ::: "memory");
        __syncthreads();
        const uint32_t stb = sb + OFF_STAGE + (s & 1) * STAGE_SZ;

        // ---- A fragments (16 rows, mt=1) ----
        uint32_t AH[2][4], AL[2][4];
        const int r0 = wm * 16 + fr;
#pragma unroll
        for (int ks = 0; ks < 2; ks++) {
            uint32_t ab = stb + (uint32_t)r0 * PITCH_B
                        + (uint32_t)(ks * 16 + fc * 2) * 4;
            lds_v2(ab,                  AH[ks][0], AH[ks][2]);
            lds_v2(ab + 8 * PITCH_B,    AH[ks][1], AH[ks][3]);
            lds_v2(ab + 32,             AL[ks][0], AL[ks][2]);
            lds_v2(ab + 8 * PITCH_B + 32, AL[ks][1], AL[ks][3]);
        }

        // ---- N tiles ----
#pragma unroll
        for (int nt = 0; nt < 8; nt++) {
            const int n = (wn * 8 + nt) * 8 + fr;
            uint32_t bb = stb + A_SMEM + (uint32_t)n * PITCH_B + fc * 8;
            uint32_t BH[2][2], BL[2][2];
            lds_v2(bb,      BH[0][0], BH[0][1]);   // ks0 h0
            lds_v2(bb + 32, BL[0][0], BL[0][1]);   // ks0 h1
            lds_v2(bb + 64, BH[1][0], BH[1][1]);   // ks1 h0
            lds_v2(bb + 96, BL[1][0], BL[1][1]);   // ks1 h1

            float tm[4], tc0[4], tc1[4];
            mma_zro(tm,  AH[0], BH[0][0], BH[0][1]);  // h0*h0 ks0
            mma_acc(tm,  AH[1], BH[1][0], BH[1][1]);  // h0*h0 ks1
            mma_zro(tc0, AH[0], BL[0][0], BL[0][1]);  // h0*h1 ks0
            mma_acc(tc0, AL[0], BH[0][0], BH[0][1]);  // h1*h0 ks0
            mma_zro(tc1, AH[1], BL[1][0], BL[1][1]);  // h0*h1 ks1
            mma_acc(tc1, AL[1], BH[1][0], BH[1][1]);  // h1*h0 ks1
#pragma unroll
            for (int q = 0; q < 4; q++)
                acc[nt][q] += tm[q] + tc0[q] + tc1[q];
        }

        __syncthreads();
        if (s + 2 < NST) ISSUE(s + 2);
        asm volatile("cp.async.commit_group;" ::: "memory");
    }
#undef ISSUE

    // ---- write logits (unscale by 1/64) ----
    {
        const float inv = 1.0f / 64.0f;
        const int r = wm * 16 + fr;
#pragma unroll
        for (int nt = 0; nt < 8; nt++) {
            int c = n0 + (wn * 8 + nt) * 8 + fc * 2;
            *(float2*)&g_logits[(size_t)(m0 + r) * NE + c] =
                make_float2(acc[nt][0] * inv, acc[nt][1] * inv);
            *(float2*)&g_logits[(size_t)(m0 + r + 8) * NE + c] =
                make_float2(acc[nt][2] * inv, acc[nt][3] * inv);
        }
    }
}

// ---------------- gate kernel (R2-proven, warp per token) ------------------
__global__ void gate_kernel(const float* __restrict__ bias,
                            float* __restrict__ out, int T)
{
    const int gw   = (int)((blockIdx.x * blockDim.x + threadIdx.x) >> 5);
    const int lane = threadIdx.x & 31;
    if (gw >= T) return;

    const float* lg = g_logits + (size_t)gw * NE;
    const unsigned FULL = 0xffffffffu;

    float s[8], v[8];
#pragma unroll
    for (int j = 0; j < 8; j++) {
        float x  = lg[j * 32 + lane];
        float sc = 1.0f / (1.0f + expf(-x));
        s[j] = sc;
        v[j] = sc + bias[j * 32 + lane];
    }

    float gs[8];
#pragma unroll
    for (int j = 0; j < 8; j++) {
        float m1 = v[j], m2 = -3.402823e38f;
#pragma unroll
        for (int off = 16; off > 0; off >>= 1) {
            float o1 = __shfl_xor_sync(FULL, m1, off);
            float o2 = __shfl_xor_sync(FULL, m2, off);
            float nm1 = fmaxf(m1, o1);
            float nm2 = fmaxf(fminf(m1, o1), fmaxf(m2, o2));
            m1 = nm1; m2 = nm2;
        }
        gs[j] = m1 + m2;
    }

    unsigned sel = 0;
#pragma unroll
    for (int j = 0; j < 8; j++) {
        int rank = 0;
#pragma unroll
        for (int j2 = 0; j2 < 8; j2++)
            rank += (gs[j2] > gs[j]) || (gs[j2] == gs[j] && j2 < j);
        if (rank < 4) sel |= (1u << j);
    }

    float tmp[8];
#pragma unroll
    for (int j = 0; j < 8; j++)
        tmp[j] = ((sel >> j) & 1u) ? v[j] : 0.0f;

    float my_w = 0.0f, wsum = 0.0f;
    int   my_e = 0;
#pragma unroll
    for (int slot = 0; slot < 8; slot++) {
        float bv = -3.402823e38f;
        int   be = 1 << 20;
#pragma unroll
        for (int j = 0; j < 8; j++) {
            if (tmp[j] > bv) { bv = tmp[j]; be = j * 32 + lane; }
        }
#pragma unroll
        for (int off = 16; off > 0; off >>= 1) {
            float ov = __shfl_xor_sync(FULL, bv, off);
            int   oe = __shfl_xor_sync(FULL, be, off);
            if (ov > bv || (ov == bv && oe < be)) { bv = ov; be = oe; }
        }
        const int jwin = be >> 5, lwin = be & 31;
        float sv_local = s[0];
#pragma unroll
        for (int j = 1; j < 8; j++)
            if (j == jwin) sv_local = s[j];
        float sv = __shfl_sync(FULL, sv_local, lwin);

        wsum += sv;
        if (lane == slot) { my_e = be; my_w = sv; }
        if (lane == lwin) {
#pragma unroll
            for (int j = 0; j < 8; j++)
                if (j == jwin) tmp[j] = -3.402823e38f;
        }
    }

    if (lane < 8) {
        out[(size_t)gw * 8 + lane] = (float)my_e;
        out[(size_t)T * 8 + (size_t)gw * 8 + lane] =
            my_w / (wsum + 1e-20f) * 2.5f;
    }
}

extern "C" void kernel_launch(void* const* d_in, const int* in_sizes, int n_in,
                              void* d_out, int out_size)
{
    const float* X    = (const float*)d_in[0];
    const float* W    = (const float*)d_in[1];
    const float* bias = (const float*)d_in[2];
    float* out = (float*)d_out;

    const int T = in_sizes[0] / KD;   // 16384

    xsplit_kernel<<<T, 256>>>(X, T);
    wsplit_kernel<<<(128 * 256 * 32) / 256, 256>>>(W);

    cudaFuncSetAttribute(gemm_kernel,
                         cudaFuncAttributeMaxDynamicSharedMemorySize, SMEM_TOTAL);
    gemm_kernel<<<(T / 64) * 2, 256, SMEM_TOTAL>>>(T);

    gate_kernel<<<(T * 32 + 255) / 256, 256>>>(bias, out, T);
}

// round 13
// speedup vs baseline: 1.1463x; 1.0715x over previous
#include <cuda_runtime.h>
#include <cuda_fp16.h>
#include <cstdint>

// ---------------------------------------------------------------------------
// MoE gate, split-N x4 for occupancy: GEMM CTAs cover 64 tokens x 64 experts
// (acc=16 regs/thread, 4 CTAs/SM = 32 warps/SM), logits to global scratch,
// warp-per-token gate kernel (R2-proven). Numerics = R10/R12 (bit-identical):
//   x*(64w) = h0x*h0w + h0x*h1w + h1x*h0w, per-K32 tm/tc0/tc1 2-chains,
//   long-range K accumulation in fp32 FADDs.
// out (float32): [0..T*8) = topk_idx (as float), [T*8..2T*8) = weights*2.5
// ---------------------------------------------------------------------------

#define KD    4096
#define NE    256
#define NST   128                 // K32 stages
#define TMAX  16384

#define PITCH_B   160             // bytes per row: 32 u32 data + 8 pad words
#define A_SMEM    (64 * PITCH_B)                // 10240
#define B_SMEM    (64 * PITCH_B)                // 10240
#define STAGE_SZ  (A_SMEM + B_SMEM)             // 20480
#define OFF_STAGE 1024
#define SMEM_TOTAL (OFF_STAGE + 2 * STAGE_SZ)   // 41984

// images: [(row_kb)*32 + word], word = ks*16 + plane*8 + pos,
//         pair p at pos = ((p&1)<<2)|(p>>1)
__device__ __align__(16) uint32_t g_xsplit[(size_t)TMAX * 128 * 32]; // 256 MB
__device__ __align__(16) uint32_t g_wsplit[(size_t)128 * 256 * 32];  //   4 MB
__device__ __align__(16) float    g_logits[(size_t)TMAX * NE];       //  16 MB

__device__ __forceinline__ uint32_t smem_u32(const void* p) {
    uint32_t a;
    asm("{ .reg .u64 t; cvta.to.shared.u64 t, %1; cvt.u32.u64 %0, t; }"
        : "=r"(a) : "l"(p));
    return a;
}
__device__ __forceinline__ void lds_v2(uint32_t a, uint32_t& x, uint32_t& y) {
    asm volatile("ld.shared.v2.u32 {%0,%1}, [%2];" : "=r"(x), "=r"(y) : "r"(a));
}
__device__ __forceinline__ void mma_acc(float* d, const uint32_t* a,
                                        uint32_t b0, uint32_t b1) {
    asm volatile(
        "mma.sync.aligned.m16n8k16.row.col.f32.f16.f16.f32 "
        "{%0,%1,%2,%3}, {%4,%5,%6,%7}, {%8,%9}, {%0,%1,%2,%3};"
        : "+f"(d[0]), "+f"(d[1]), "+f"(d[2]), "+f"(d[3])
        : "r"(a[0]), "r"(a[1]), "r"(a[2]), "r"(a[3]), "r"(b0), "r"(b1));
}
__device__ __forceinline__ void mma_zro(float* d, const uint32_t* a,
                                        uint32_t b0, uint32_t b1) {
    asm volatile(
        "mma.sync.aligned.m16n8k16.row.col.f32.f16.f16.f32 "
        "{%0,%1,%2,%3}, {%4,%5,%6,%7}, {%8,%9}, {%10,%11,%12,%13};"
        : "=f"(d[0]), "=f"(d[1]), "=f"(d[2]), "=f"(d[3])
        : "r"(a[0]), "r"(a[1]), "r"(a[2]), "r"(a[3]), "r"(b0), "r"(b1),
          "f"(0.0f), "f"(0.0f), "f"(0.0f), "f"(0.0f));
}

// ---------------- vectorized X pre-split (R10-proven) ----------------------
__global__ __launch_bounds__(256)
void xsplit_kernel(const float* __restrict__ X, int T) {
    size_t id = (size_t)blockIdx.x * 256 + threadIdx.x;
    int half = (int)(id & 1);
    int kb   = (int)((id >> 1) & 127);
    size_t m = id >> 8;
    if (m >= (size_t)T) return;

    const float4* src = (const float4*)(X + m * KD + kb * 32 + half * 16);
    float4 f0 = src[0], f1 = src[1], f2 = src[2], f3 = src[3];
    float x[16] = {f0.x,f0.y,f0.z,f0.w, f1.x,f1.y,f1.z,f1.w,
                   f2.x,f2.y,f2.z,f2.w, f3.x,f3.y,f3.z,f3.w};
    uint32_t p0[8], p1[8];
#pragma unroll
    for (int p = 0; p < 8; p++) {
        float a = x[2*p], b = x[2*p+1];
        __half2 h0 = __floats2half2_rn(a, b);
        p0[p] = *reinterpret_cast<uint32_t*>(&h0);
        float r0 = a - __half2float(__low2half(h0));
        float r1 = b - __half2float(__high2half(h0));
        __half2 h1 = __floats2half2_rn(r0, r1);
        p1[p] = *reinterpret_cast<uint32_t*>(&h1);
    }
    uint4* dst = (uint4*)(g_xsplit + ((m * 128 + kb) * 32) + half * 16);
    dst[0] = make_uint4(p0[0], p0[4], p0[1], p0[5]);
    dst[1] = make_uint4(p0[2], p0[6], p0[3], p0[7]);
    dst[2] = make_uint4(p1[0], p1[4], p1[1], p1[5]);
    dst[3] = make_uint4(p1[2], p1[6], p1[3], p1[7]);
}

// ---------------- W pre-split (scaled by 64; unscaled later) ---------------
__global__ __launch_bounds__(256)
void wsplit_kernel(const float* __restrict__ W) {
    size_t id = (size_t)blockIdx.x * 256 + threadIdx.x;   // 128*256*32
    int w  = (int)(id & 31);
    size_t rn = id >> 5;
    int n  = (int)(rn & 255);
    int kb = (int)(rn >> 8);
    int half = w >> 4, plane = (w >> 3) & 1, pos = w & 7;
    int p = ((pos & 1) << 2) | (pos >> 1);
    int k = kb * 32 + half * 16 + p * 2;
    float x0 = W[(size_t)n * KD + k] * 64.0f;
    float x1 = W[(size_t)n * KD + k + 1] * 64.0f;
    __half2 h0 = __floats2half2_rn(x0, x1);
    uint32_t v;
    if (plane == 0) v = *reinterpret_cast<uint32_t*>(&h0);
    else {
        float r0 = x0 - __half2float(__low2half(h0));
        float r1 = x1 - __half2float(__high2half(h0));
        __half2 h1 = __floats2half2_rn(r0, r1);
        v = *reinterpret_cast<uint32_t*>(&h1);
    }
    g_wsplit[id] = v;
}

// ------------------------------- GEMM kernel -------------------------------
// grid: bid = m_tile * 4 + n_tile  (n-split CTAs adjacent -> co-resident,
// X image hits L2 for 3 of 4 readers)
__global__ __launch_bounds__(256, 4)
void gemm_kernel(int T)
{
    extern __shared__ char sm[];
    const uint32_t sb = smem_u32(sm);
    const int tid = threadIdx.x, wid = tid >> 5, lane = tid & 31;
    const int wm = wid & 3, wn = wid >> 2;           // 4x2 warp grid
    const int m0 = (blockIdx.x >> 2) * 64;
    const int n0 = (blockIdx.x & 3) * 64;
    const int fr = lane >> 2, fc = lane & 3;

#define ISSUE(s) do {                                                          \
    uint32_t stb_ = sb + OFF_STAGE + ((s) & 1) * STAGE_SZ;                     \
    _Pragma("unroll")                                                          \
    for (int i_ = 0; i_ < 2; i_++) {       /* A image: 64 rows x 128B */       \
        int id_ = tid + i_ * 256;                                              \
        int r_ = id_ >> 3, c_ = id_ & 7;                                       \
        const uint32_t* src_ = g_xsplit                                        \
            + ((size_t)(m0 + r_) * 128 + (s)) * 32 + c_ * 4;                   \
        asm volatile("cp.async.cg.shared.global [%0], [%1], 16;"               \
            :: "r"(stb_ + r_ * PITCH_B + c_ * 16), "l"(src_));                 \
    }                                                                          \
    _Pragma("unroll")                                                          \
    for (int i_ = 0; i_ < 2; i_++) {       /* B image: 64 rows x 128B */       \
        int id_ = tid + i_ * 256;                                              \
        int n_ = id_ >> 3, c_ = id_ & 7;                                       \
        const uint32_t* src_ = g_wsplit                                        \
            + ((size_t)(s) * 256 + n0 + n_) * 32 + c_ * 4;                     \
        asm volatile("cp.async.cg.shared.global [%0], [%1], 16;"               \
            :: "r"(stb_ + A_SMEM + n_ * PITCH_B + c_ * 16), "l"(src_));        \
    }                                                                          \
} while (0)

    ISSUE(0); asm volatile("cp.async.commit_group;" ::: "memory");
    ISSUE(1); asm volatile("cp.async.commit_group;" ::: "memory");

    float acc[4][4];
#pragma unroll
    for (int j = 0; j < 4; j++)
#pragma unroll
        for (int q = 0; q < 4; q++) acc[j][q] = 0.0f;

    for (int s = 0; s < NST; s++) {
        asm volatile("cp.async.wait_group 1;" ::: "memory");
        __syncthreads();
        const uint32_t stb = sb + OFF_STAGE + (s & 1) * STAGE_SZ;

        // ---- A fragments (16 rows) ----
        uint32_t AH[2][4], AL[2][4];
        const int r0 = wm * 16 + fr;
#pragma unroll
        for (int ks = 0; ks < 2; ks++) {
            uint32_t ab = stb + (uint32_t)r0 * PITCH_B
                        + (uint32_t)(ks * 16 + fc * 2) * 4;
            lds_v2(ab,                    AH[ks][0], AH[ks][2]);
            lds_v2(ab + 8 * PITCH_B,      AH[ks][1], AH[ks][3]);
            lds_v2(ab + 32,               AL[ks][0], AL[ks][2]);
            lds_v2(ab + 8 * PITCH_B + 32, AL[ks][1], AL[ks][3]);
        }

        // ---- N tiles (4 per warp) ----
#pragma unroll
        for (int nt = 0; nt < 4; nt++) {
            const int n = wn * 32 + nt * 8 + fr;
            uint32_t bb = stb + A_SMEM + (uint32_t)n * PITCH_B + fc * 8;
            uint32_t BH[2][2], BL[2][2];
            lds_v2(bb,      BH[0][0], BH[0][1]);   // ks0 h0
            lds_v2(bb + 32, BL[0][0], BL[0][1]);   // ks0 h1
            lds_v2(bb + 64, BH[1][0], BH[1][1]);   // ks1 h0
            lds_v2(bb + 96, BL[1][0], BL[1][1]);   // ks1 h1

            float tm[4], tc0[4], tc1[4];
            mma_zro(tm,  AH[0], BH[0][0], BH[0][1]);  // h0*h0 ks0
            mma_acc(tm,  AH[1], BH[1][0], BH[1][1]);  // h0*h0 ks1
            mma_zro(tc0, AH[0], BL[0][0], BL[0][1]);  // h0*h1 ks0
            mma_acc(tc0, AL[0], BH[0][0], BH[0][1]);  // h1*h0 ks0
            mma_zro(tc1, AH[1], BL[1][0], BL[1][1]);  // h0*h1 ks1
            mma_acc(tc1, AL[1], BH[1][0], BH[1][1]);  // h1*h0 ks1
#pragma unroll
            for (int q = 0; q < 4; q++)
                acc[nt][q] += tm[q] + tc0[q] + tc1[q];
        }

        __syncthreads();
        if (s + 2 < NST) ISSUE(s + 2);
        asm volatile("cp.async.commit_group;" ::: "memory");
    }
#undef ISSUE

    // ---- write logits (unscale by 1/64) ----
    {
        const float inv = 1.0f / 64.0f;
        const int r = wm * 16 + fr;
#pragma unroll
        for (int nt = 0; nt < 4; nt++) {
            int c = n0 + wn * 32 + nt * 8 + fc * 2;
            *(float2*)&g_logits[(size_t)(m0 + r) * NE + c] =
                make_float2(acc[nt][0] * inv, acc[nt][1] * inv);
            *(float2*)&g_logits[(size_t)(m0 + r + 8) * NE + c] =
                make_float2(acc[nt][2] * inv, acc[nt][3] * inv);
        }
    }
}

// ---------------- gate kernel (R2-proven, warp per token) ------------------
__global__ void gate_kernel(const float* __restrict__ bias,
                            float* __restrict__ out, int T)
{
    const int gw   = (int)((blockIdx.x * blockDim.x + threadIdx.x) >> 5);
    const int lane = threadIdx.x & 31;
    if (gw >= T) return;

    const float* lg = g_logits + (size_t)gw * NE;
    const unsigned FULL = 0xffffffffu;

    float s[8], v[8];
#pragma unroll
    for (int j = 0; j < 8; j++) {
        float x  = lg[j * 32 + lane];
        float sc = 1.0f / (1.0f + expf(-x));
        s[j] = sc;
        v[j] = sc + bias[j * 32 + lane];
    }

    float gs[8];
#pragma unroll
    for (int j = 0; j < 8; j++) {
        float m1 = v[j], m2 = -3.402823e38f;
#pragma unroll
        for (int off = 16; off > 0; off >>= 1) {
            float o1 = __shfl_xor_sync(FULL, m1, off);
            float o2 = __shfl_xor_sync(FULL, m2, off);
            float nm1 = fmaxf(m1, o1);
            float nm2 = fmaxf(fminf(m1, o1), fmaxf(m2, o2));
            m1 = nm1; m2 = nm2;
        }
        gs[j] = m1 + m2;
    }

    unsigned sel = 0;
#pragma unroll
    for (int j = 0; j < 8; j++) {
        int rank = 0;
#pragma unroll
        for (int j2 = 0; j2 < 8; j2++)
            rank += (gs[j2] > gs[j]) || (gs[j2] == gs[j] && j2 < j);
        if (rank < 4) sel |= (1u << j);
    }

    float tmp[8];
#pragma unroll
    for (int j = 0; j < 8; j++)
        tmp[j] = ((sel >> j) & 1u) ? v[j] : 0.0f;

    float my_w = 0.0f, wsum = 0.0f;
    int   my_e = 0;
#pragma unroll
    for (int slot = 0; slot < 8; slot++) {
        float bv = -3.402823e38f;
        int   be = 1 << 20;
#pragma unroll
        for (int j = 0; j < 8; j++) {
            if (tmp[j] > bv) { bv = tmp[j]; be = j * 32 + lane; }
        }
#pragma unroll
        for (int off = 16; off > 0; off >>= 1) {
            float ov = __shfl_xor_sync(FULL, bv, off);
            int   oe = __shfl_xor_sync(FULL, be, off);
            if (ov > bv || (ov == bv && oe < be)) { bv = ov; be = oe; }
        }
        const int jwin = be >> 5, lwin = be & 31;
        float sv_local = s[0];
#pragma unroll
        for (int j = 1; j < 8; j++)
            if (j == jwin) sv_local = s[j];
        float sv = __shfl_sync(FULL, sv_local, lwin);

        wsum += sv;
        if (lane == slot) { my_e = be; my_w = sv; }
        if (lane == lwin) {
#pragma unroll
            for (int j = 0; j < 8; j++)
                if (j == jwin) tmp[j] = -3.402823e38f;
        }
    }

    if (lane < 8) {
        out[(size_t)gw * 8 + lane] = (float)my_e;
        out[(size_t)T * 8 + (size_t)gw * 8 + lane] =
            my_w / (wsum + 1e-20f) * 2.5f;
    }
}

extern "C" void kernel_launch(void* const* d_in, const int* in_sizes, int n_in,
                              void* d_out, int out_size)
{
    const float* X    = (const float*)d_in[0];
    const float* W    = (const float*)d_in[1];
    const float* bias = (const float*)d_in[2];
    float* out = (float*)d_out;

    const int T = in_sizes[0] / KD;   // 16384

    xsplit_kernel<<<T, 256>>>(X, T);
    wsplit_kernel<<<(128 * 256 * 32) / 256, 256>>>(W);

    cudaFuncSetAttribute(gemm_kernel,
                         cudaFuncAttributeMaxDynamicSharedMemorySize, SMEM_TOTAL);
    gemm_kernel<<<(T / 64) * 4, 256, SMEM_TOTAL>>>(T);

    gate_kernel<<<(T * 32 + 255) / 256, 256>>>(bias, out, T);
}

// round 14
// speedup vs baseline: 1.2176x; 1.0622x over previous
#include <cuda_runtime.h>
#include <cuda_fp16.h>
#include <cstdint>

// ---------------------------------------------------------------------------
// MoE gate, split-N x4 (64tok x 64exp CTAs, 4/SM), LDS.128 fragment images,
// tc merged to one balanced 4-chain (R7-validated), 2 FADD folds/elem.
//   x*(64w) = h0x*h0w (2-chain tm) + [h0x*h1w + h1x*h0w over ks0,ks1] (4-chain tc)
//   long-range K accumulation in fp32 FADDs.
// out (float32): [0..T*8) = topk_idx (as float), [T*8..2T*8) = weights*2.5
// ---------------------------------------------------------------------------

#define KD    4096
#define NE    256
#define NST   128                 // K32 stages
#define TMAX  16384

#define PITCH_B   192             // bytes/row: 32 data words + 16 pad words
#define A_SMEM    (64 * PITCH_B)                // 12288
#define B_SMEM    (64 * PITCH_B)                // 12288
#define STAGE_SZ  (A_SMEM + B_SMEM)             // 24576
#define OFF_STAGE 1024
#define SMEM_TOTAL (OFF_STAGE + 2 * STAGE_SZ)   // 50176

// Row image per (row, K32-block): 32 u32 words,
//   word = ks*16 + fc*4 + j,  fc = 0..3,
//   j: 0 = h0 pair k=fc*2, 1 = h0 pair k=fc*2+8, 2 = h1 pair k=fc*2,
//      3 = h1 pair k=fc*2+8    (k within the ks-th k16 block)
__device__ __align__(16) uint32_t g_xsplit[(size_t)TMAX * 128 * 32]; // 256 MB
__device__ __align__(16) uint32_t g_wsplit[(size_t)128 * 256 * 32];  //   4 MB
__device__ __align__(16) float    g_logits[(size_t)TMAX * NE];       //  16 MB

__device__ __forceinline__ uint32_t smem_u32(const void* p) {
    uint32_t a;
    asm("{ .reg .u64 t; cvta.to.shared.u64 t, %1; cvt.u32.u64 %0, t; }"
        : "=r"(a) : "l"(p));
    return a;
}
__device__ __forceinline__ void lds_v4(uint32_t a, uint32_t& x, uint32_t& y,
                                       uint32_t& z, uint32_t& w) {
    asm volatile("ld.shared.v4.u32 {%0,%1,%2,%3}, [%4];"
                 : "=r"(x), "=r"(y), "=r"(z), "=r"(w) : "r"(a));
}
__device__ __forceinline__ void mma_acc(float* d, const uint32_t* a,
                                        uint32_t b0, uint32_t b1) {
    asm volatile(
        "mma.sync.aligned.m16n8k16.row.col.f32.f16.f16.f32 "
        "{%0,%1,%2,%3}, {%4,%5,%6,%7}, {%8,%9}, {%0,%1,%2,%3};"
        : "+f"(d[0]), "+f"(d[1]), "+f"(d[2]), "+f"(d[3])
        : "r"(a[0]), "r"(a[1]), "r"(a[2]), "r"(a[3]), "r"(b0), "r"(b1));
}
__device__ __forceinline__ void mma_zro(float* d, const uint32_t* a,
                                        uint32_t b0, uint32_t b1) {
    asm volatile(
        "mma.sync.aligned.m16n8k16.row.col.f32.f16.f16.f32 "
        "{%0,%1,%2,%3}, {%4,%5,%6,%7}, {%8,%9}, {%10,%11,%12,%13};"
        : "=f"(d[0]), "=f"(d[1]), "=f"(d[2]), "=f"(d[3])
        : "r"(a[0]), "r"(a[1]), "r"(a[2]), "r"(a[3]), "r"(b0), "r"(b1),
          "f"(0.0f), "f"(0.0f), "f"(0.0f), "f"(0.0f));
}

// ---------------- X pre-split: one (m, kb, half) per thread ----------------
__global__ __launch_bounds__(256)
void xsplit_kernel(const float* __restrict__ X, int T) {
    size_t id = (size_t)blockIdx.x * 256 + threadIdx.x;
    int half = (int)(id & 1);                 // ks
    int kb   = (int)((id >> 1) & 127);
    size_t m = id >> 8;
    if (m >= (size_t)T) return;

    const float4* src = (const float4*)(X + m * KD + kb * 32 + half * 16);
    float4 f0 = src[0], f1 = src[1], f2 = src[2], f3 = src[3];
    float x[16] = {f0.x,f0.y,f0.z,f0.w, f1.x,f1.y,f1.z,f1.w,
                   f2.x,f2.y,f2.z,f2.w, f3.x,f3.y,f3.z,f3.w};
    uint32_t p0[8], p1[8];
#pragma unroll
    for (int p = 0; p < 8; p++) {
        float a = x[2*p], b = x[2*p+1];
        __half2 h0 = __floats2half2_rn(a, b);
        p0[p] = *reinterpret_cast<uint32_t*>(&h0);
        float r0 = a - __half2float(__low2half(h0));
        float r1 = b - __half2float(__high2half(h0));
        __half2 h1 = __floats2half2_rn(r0, r1);
        p1[p] = *reinterpret_cast<uint32_t*>(&h1);
    }
    // word fc*4+{0,1,2,3} = {p0[fc], p0[fc+4], p1[fc], p1[fc+4]}
    uint4* dst = (uint4*)(g_xsplit + ((m * 128 + kb) * 32) + half * 16);
#pragma unroll
    for (int fc = 0; fc < 4; fc++)
        dst[fc] = make_uint4(p0[fc], p0[fc+4], p1[fc], p1[fc+4]);
}

// ---------------- W pre-split (scaled by 64; unscaled later) ---------------
__global__ __launch_bounds__(256)
void wsplit_kernel(const float* __restrict__ W) {
    size_t id = (size_t)blockIdx.x * 256 + threadIdx.x;   // 128*256*2 total
    int half = (int)(id & 1);
    int n    = (int)((id >> 1) & 255);
    int kb   = (int)(id >> 9);

    const float4* src = (const float4*)(W + (size_t)n * KD + kb * 32 + half * 16);
    float4 f0 = src[0], f1 = src[1], f2 = src[2], f3 = src[3];
    float x[16] = {f0.x,f0.y,f0.z,f0.w, f1.x,f1.y,f1.z,f1.w,
                   f2.x,f2.y,f2.z,f2.w, f3.x,f3.y,f3.z,f3.w};
    uint32_t p0[8], p1[8];
#pragma unroll
    for (int p = 0; p < 8; p++) {
        float a = x[2*p] * 64.0f, b = x[2*p+1] * 64.0f;
        __half2 h0 = __floats2half2_rn(a, b);
        p0[p] = *reinterpret_cast<uint32_t*>(&h0);
        float r0 = a - __half2float(__low2half(h0));
        float r1 = b - __half2float(__high2half(h0));
        __half2 h1 = __floats2half2_rn(r0, r1);
        p1[p] = *reinterpret_cast<uint32_t*>(&h1);
    }
    uint4* dst = (uint4*)(g_wsplit + (((size_t)kb * 256 + n) * 32) + half * 16);
#pragma unroll
    for (int fc = 0; fc < 4; fc++)
        dst[fc] = make_uint4(p0[fc], p0[fc+4], p1[fc], p1[fc+4]);
}

// ------------------------------- GEMM kernel -------------------------------
// grid: bid = m_tile * 4 + n_tile
__global__ __launch_bounds__(256, 4)
void gemm_kernel(int T)
{
    extern __shared__ char sm[];
    const uint32_t sb = smem_u32(sm);
    const int tid = threadIdx.x, wid = tid >> 5, lane = tid & 31;
    const int wm = wid & 3, wn = wid >> 2;           // 4x2 warp grid
    const int m0 = (blockIdx.x >> 2) * 64;
    const int n0 = (blockIdx.x & 3) * 64;
    const int fr = lane >> 2, fc = lane & 3;

#define ISSUE(s) do {                                                          \
    uint32_t stb_ = sb + OFF_STAGE + ((s) & 1) * STAGE_SZ;                     \
    _Pragma("unroll")                                                          \
    for (int i_ = 0; i_ < 2; i_++) {       /* A image: 64 rows x 128B */       \
        int id_ = tid + i_ * 256;                                              \
        int r_ = id_ >> 3, c_ = id_ & 7;                                       \
        const uint32_t* src_ = g_xsplit                                        \
            + ((size_t)(m0 + r_) * 128 + (s)) * 32 + c_ * 4;                   \
        asm volatile("cp.async.cg.shared.global [%0], [%1], 16;"               \
            :: "r"(stb_ + r_ * PITCH_B + c_ * 16), "l"(src_));                 \
    }                                                                          \
    _Pragma("unroll")                                                          \
    for (int i_ = 0; i_ < 2; i_++) {       /* B image: 64 rows x 128B */       \
        int id_ = tid + i_ * 256;                                              \
        int n_ = id_ >> 3, c_ = id_ & 7;                                       \
        const uint32_t* src_ = g_wsplit                                        \
            + (((size_t)(s) * 256) + n0 + n_) * 32 + c_ * 4;                   \
        asm volatile("cp.async.cg.shared.global [%0], [%1], 16;"               \
            :: "r"(stb_ + A_SMEM + n_ * PITCH_B + c_ * 16), "l"(src_));        \
    }                                                                          \
} while (0)

    ISSUE(0); asm volatile("cp.async.commit_group;" ::: "memory");
    ISSUE(1); asm volatile("cp.async.commit_group;" ::: "memory");

    float acc[4][4];
#pragma unroll
    for (int j = 0; j < 4; j++)
#pragma unroll
        for (int q = 0; q < 4; q++) acc[j][q] = 0.0f;

    for (int s = 0; s < NST; s++) {
        asm volatile("cp.async.wait_group 1;" ::: "memory");
        __syncthreads();
        const uint32_t stb = sb + OFF_STAGE + (s & 1) * STAGE_SZ;

        // ---- A fragments: per ks, v4 from row r0 and row r0+8 ----
        // row r0 v4   = {a0h, a2h, a0l, a2l}
        // row r0+8 v4 = {a1h, a3h, a1l, a3l}
        uint32_t AH[2][4], AL[2][4];
        const int r0 = wm * 16 + fr;
#pragma unroll
        for (int ks = 0; ks < 2; ks++) {
            uint32_t ab = stb + (uint32_t)r0 * PITCH_B + ks * 64 + fc * 16;
            uint32_t x0, y0, z0, w0, x1, y1, z1, w1;
            lds_v4(ab,                x0, y0, z0, w0);
            lds_v4(ab + 8 * PITCH_B,  x1, y1, z1, w1);
            AH[ks][0] = x0; AH[ks][1] = x1; AH[ks][2] = y0; AH[ks][3] = y1;
            AL[ks][0] = z0; AL[ks][1] = z1; AL[ks][2] = w0; AL[ks][3] = w1;
        }

        // ---- N tiles (4 per warp) ----
#pragma unroll
        for (int nt = 0; nt < 4; nt++) {
            const int n = wn * 32 + nt * 8 + fr;
            uint32_t bb = stb + A_SMEM + (uint32_t)n * PITCH_B + fc * 16;
            uint32_t b0h0, b1h0, b0l0, b1l0, b0h1, b1h1, b0l1, b1l1;
            lds_v4(bb,      b0h0, b1h0, b0l0, b1l0);   // ks0: {b0h,b1h,b0l,b1l}
            lds_v4(bb + 64, b0h1, b1h1, b0l1, b1l1);   // ks1

            float tm[4], tc[4];
            mma_zro(tm, AH[0], b0h0, b1h0);   // h0*h0 ks0
            mma_acc(tm, AH[1], b0h1, b1h1);   // h0*h0 ks1
            mma_zro(tc, AH[0], b0l0, b1l0);   // h0*h1 ks0
            mma_acc(tc, AL[0], b0h0, b1h0);   // h1*h0 ks0
            mma_acc(tc, AH[1], b0l1, b1l1);   // h0*h1 ks1
            mma_acc(tc, AL[1], b0h1, b1h1);   // h1*h0 ks1
#pragma unroll
            for (int q = 0; q < 4; q++)
                acc[nt][q] += tm[q] + tc[q];
        }

        __syncthreads();
        if (s + 2 < NST) ISSUE(s + 2);
        asm volatile("cp.async.commit_group;" ::: "memory");
    }
#undef ISSUE

    // ---- write logits (unscale by 1/64) ----
    {
        const float inv = 1.0f / 64.0f;
        const int r = wm * 16 + fr;
#pragma unroll
        for (int nt = 0; nt < 4; nt++) {
            int c = n0 + wn * 32 + nt * 8 + fc * 2;
            *(float2*)&g_logits[(size_t)(m0 + r) * NE + c] =
                make_float2(acc[nt][0] * inv, acc[nt][1] * inv);
            *(float2*)&g_logits[(size_t)(m0 + r + 8) * NE + c] =
                make_float2(acc[nt][2] * inv, acc[nt][3] * inv);
        }
    }
}

// ---------------- gate kernel (R2-proven, warp per token) ------------------
__global__ void gate_kernel(const float* __restrict__ bias,
                            float* __restrict__ out, int T)
{
    const int gw   = (int)((blockIdx.x * blockDim.x + threadIdx.x) >> 5);
    const int lane = threadIdx.x & 31;
    if (gw >= T) return;

    const float* lg = g_logits + (size_t)gw * NE;
    const unsigned FULL = 0xffffffffu;

    float s[8], v[8];
#pragma unroll
    for (int j = 0; j < 8; j++) {
        float x  = lg[j * 32 + lane];
        float sc = 1.0f / (1.0f + expf(-x));
        s[j] = sc;
        v[j] = sc + bias[j * 32 + lane];
    }

    float gs[8];
#pragma unroll
    for (int j = 0; j < 8; j++) {
        float m1 = v[j], m2 = -3.402823e38f;
#pragma unroll
        for (int off = 16; off > 0; off >>= 1) {
            float o1 = __shfl_xor_sync(FULL, m1, off);
            float o2 = __shfl_xor_sync(FULL, m2, off);
            float nm1 = fmaxf(m1, o1);
            float nm2 = fmaxf(fminf(m1, o1), fmaxf(m2, o2));
            m1 = nm1; m2 = nm2;
        }
        gs[j] = m1 + m2;
    }

    unsigned sel = 0;
#pragma unroll
    for (int j = 0; j < 8; j++) {
        int rank = 0;
#pragma unroll
        for (int j2 = 0; j2 < 8; j2++)
            rank += (gs[j2] > gs[j]) || (gs[j2] == gs[j] && j2 < j);
        if (rank < 4) sel |= (1u << j);
    }

    float tmp[8];
#pragma unroll
    for (int j = 0; j < 8; j++)
        tmp[j] = ((sel >> j) & 1u) ? v[j] : 0.0f;

    float my_w = 0.0f, wsum = 0.0f;
    int   my_e = 0;
#pragma unroll
    for (int slot = 0; slot < 8; slot++) {
        float bv = -3.402823e38f;
        int   be = 1 << 20;
#pragma unroll
        for (int j = 0; j < 8; j++) {
            if (tmp[j] > bv) { bv = tmp[j]; be = j * 32 + lane; }
        }
#pragma unroll
        for (int off = 16; off > 0; off >>= 1) {
            float ov = __shfl_xor_sync(FULL, bv, off);
            int   oe = __shfl_xor_sync(FULL, be, off);
            if (ov > bv || (ov == bv && oe < be)) { bv = ov; be = oe; }
        }
        const int jwin = be >> 5, lwin = be & 31;
        float sv_local = s[0];
#pragma unroll
        for (int j = 1; j < 8; j++)
            if (j == jwin) sv_local = s[j];
        float sv = __shfl_sync(FULL, sv_local, lwin);

        wsum += sv;
        if (lane == slot) { my_e = be; my_w = sv; }
        if (lane == lwin) {
#pragma unroll
            for (int j = 0; j < 8; j++)
                if (j == jwin) tmp[j] = -3.402823e38f;
        }
    }

    if (lane < 8) {
        out[(size_t)gw * 8 + lane] = (float)my_e;
        out[(size_t)T * 8 + (size_t)gw * 8 + lane] =
            my_w / (wsum + 1e-20f) * 2.5f;
    }
}

extern "C" void kernel_launch(void* const* d_in, const int* in_sizes, int n_in,
                              void* d_out, int out_size)
{
    const float* X    = (const float*)d_in[0];
    const float* W    = (const float*)d_in[1];
    const float* bias = (const float*)d_in[2];
    float* out = (float*)d_out;

    const int T = in_sizes[0] / KD;   // 16384

    xsplit_kernel<<<T, 256>>>(X, T);
    wsplit_kernel<<<(128 * 256 * 2) / 256, 256>>>(W);

    cudaFuncSetAttribute(gemm_kernel,
                         cudaFuncAttributeMaxDynamicSharedMemorySize, SMEM_TOTAL);
    gemm_kernel<<<(T / 64) * 4, 256, SMEM_TOTAL>>>(T);

    gate_kernel<<<(T * 32 + 255) / 256, 256>>>(bias, out, T);
}